// round 12
// baseline (speedup 1.0000x reference)
#include <cuda_runtime.h>
#include <cuda_fp16.h>
#include <stdint.h>

#define B_  2
#define S_  2048
#define D_  1024
#define H_  16
#define HD_ 64
#define N_  (B_*S_)   // 4096

// Scratch (allocation-free rule: __device__ globals)
__device__ __half g_xh[N_*D_];
__device__ __half g_wh3[3*D_*D_];
__device__ __half g_wh[D_*D_];
__device__ __half g_qh[N_*D_];
__device__ __half g_kh[N_*D_];
__device__ __half g_vh[N_*D_];
__device__ __half g_oh[N_*D_];

// ---------------------------------------------------------------------------
// Base-PTX helpers
// ---------------------------------------------------------------------------
__device__ __forceinline__ void cp16(uint32_t dst, const void* src) {
    asm volatile("cp.async.cg.shared.global [%0], [%1], 16;"
                 :: "r"(dst), "l"(__cvta_generic_to_global(src)));
}
__device__ __forceinline__ void cp_commit() {
    asm volatile("cp.async.commit_group;");
}
template<int N> __device__ __forceinline__ void cp_wait() {
    asm volatile("cp.async.wait_group %0;" :: "n"(N));
}
__device__ __forceinline__ void mma_f16(float c[4],
                                        const uint32_t a[4],
                                        const uint32_t b[2]) {
    asm volatile(
        "mma.sync.aligned.m16n8k16.row.col.f32.f16.f16.f32 "
        "{%0,%1,%2,%3}, {%4,%5,%6,%7}, {%8,%9}, {%0,%1,%2,%3};"
        : "+f"(c[0]), "+f"(c[1]), "+f"(c[2]), "+f"(c[3])
        : "r"(a[0]), "r"(a[1]), "r"(a[2]), "r"(a[3]),
          "r"(b[0]), "r"(b[1]));
}
__device__ __forceinline__ void ldm_x4(uint32_t r[4], uint32_t a) {
    asm volatile("ldmatrix.sync.aligned.m8n8.x4.shared.b16 {%0,%1,%2,%3}, [%4];"
                 : "=r"(r[0]), "=r"(r[1]), "=r"(r[2]), "=r"(r[3]) : "r"(a));
}
__device__ __forceinline__ void ldm_x4_t(uint32_t r[4], uint32_t a) {
    asm volatile("ldmatrix.sync.aligned.m8n8.x4.trans.shared.b16 {%0,%1,%2,%3}, [%4];"
                 : "=r"(r[0]), "=r"(r[1]), "=r"(r[2]), "=r"(r[3]) : "r"(a));
}
__device__ __forceinline__ uint32_t packh2(float x, float y) {
    __half2 h = __floats2half2_rn(x, y);
    return *(uint32_t*)&h;
}
__device__ __forceinline__ uint32_t ex2_h2(uint32_t h) {
    uint32_t r;
    asm("ex2.approx.f16x2 %0, %1;" : "=r"(r) : "r"(h));
    return r;
}

// ---------------------------------------------------------------------------
// Fused prepass: convert x, Wq, Wk, Wv, Wo fp32 -> fp16 in ONE launch
// ---------------------------------------------------------------------------
#define NX4 (N_*D_/4)
#define NW4 (D_*D_/4)

__global__ __launch_bounds__(256)
void cvt_all_kernel(const float* __restrict__ x,
                    const float* __restrict__ Wq,
                    const float* __restrict__ Wk,
                    const float* __restrict__ Wv,
                    const float* __restrict__ Wo,
                    __half* __restrict__ xh,
                    __half* __restrict__ wh3,
                    __half* __restrict__ wh)
{
    int i = blockIdx.x * blockDim.x + threadIdx.x;
    const float* src; __half* dst; int off;
    if (i < NX4)              { src = x;  dst = xh;                     off = i; }
    else if (i < NX4 + NW4)   { src = Wq; dst = wh3;                    off = i - NX4; }
    else if (i < NX4 + 2*NW4) { src = Wk; dst = wh3 + (size_t)D_*D_;    off = i - NX4 - NW4; }
    else if (i < NX4 + 3*NW4) { src = Wv; dst = wh3 + (size_t)2*D_*D_;  off = i - NX4 - 2*NW4; }
    else                      { src = Wo; dst = wh;                     off = i - NX4 - 3*NW4; }
    float4 v = ((const float4*)src)[off];
    uint2 o;
    o.x = packh2(v.x, v.y);
    o.y = packh2(v.z, v.w);
    ((uint2*)dst)[off] = o;
}

// ---------------------------------------------------------------------------
// fp16 tensor-core GEMM, K chunk 64 halves, 3-stage ring, software-pipelined
// fragments: all-B-ldmatrix first, A double-buffered across k16 steps.
// ---------------------------------------------------------------------------
#define TM 128
#define TN 128
#define KCH 64
#define NCH (D_/KCH)                // 16
#define GSTG 3
#define RSB 144
#define TILE_BYTES (128*RSB)        // 18432
#define STAGE_BYTES (2*TILE_BYTES)  // 36864
#define GEMM_SMEM (GSTG*STAGE_BYTES) // 110592

__device__ __forceinline__ void load_chunk_h(const __half* __restrict__ A,
                                             const __half* __restrict__ W,
                                             int row0, int col0, int c,
                                             char* stage, int tid)
{
    if (c < NCH) {
        const uint32_t abase = (uint32_t)__cvta_generic_to_shared(stage);
        const uint32_t bbase = abase + TILE_BYTES;
        const char* asrc = (const char*)(A + (size_t)row0 * D_ + c * KCH);
        const char* bsrc = (const char*)(W + (size_t)col0 * D_ + c * KCH);
#pragma unroll
        for (int i = 0; i < 4; i++) {
            int idx = tid + (i << 8);
            int r = idx >> 3, c16 = idx & 7;
            cp16(abase + (uint32_t)(r * RSB + c16 * 16),
                 asrc + (size_t)r * (D_*2) + c16 * 16);
        }
#pragma unroll
        for (int i = 0; i < 4; i++) {
            int idx = tid + (i << 8);
            int r = idx >> 3, c16 = idx & 7;
            cp16(bbase + (uint32_t)(r * RSB + c16 * 16),
                 bsrc + (size_t)r * (D_*2) + c16 * 16);
        }
    }
    cp_commit();
}

template<int OUT_HALF>
__device__ __forceinline__ void gemm_body_h(const __half* __restrict__ A,
                                            const __half* __restrict__ W,
                                            const float* __restrict__ bias,
                                            void* __restrict__ C,
                                            int row0, int col0, char* sm)
{
    const int tid  = threadIdx.x;
    const int lane = tid & 31;
    const int warp = tid >> 5;
    const int wm   = warp & 3;
    const int wn   = warp >> 2;
    const int gr = lane >> 2;
    const int lc = lane & 3;

    const uint32_t aoff = (uint32_t)((wm * 32 + (lane & 15)) * RSB + (lane >> 4) * 16);
    const uint32_t boff = (uint32_t)((wn * 64 + (lane & 7) + ((lane >> 4) << 3)) * RSB
                                     + ((lane >> 3) & 1) * 16);
    const uint32_t smb = (uint32_t)__cvta_generic_to_shared(sm);

    float c_f[2][8][4];
#pragma unroll
    for (int mi = 0; mi < 2; mi++)
#pragma unroll
        for (int ni = 0; ni < 8; ni++)
#pragma unroll
            for (int j = 0; j < 4; j++) c_f[mi][ni][j] = 0.f;

    load_chunk_h(A, W, row0, col0, 0, sm, tid);
    load_chunk_h(A, W, row0, col0, 1, sm + STAGE_BYTES, tid);

    int stg = 0;
    for (int kt = 0; kt < NCH; kt++) {
        cp_wait<GSTG - 2>();
        __syncthreads();

        int wst = stg + 2; if (wst >= GSTG) wst -= GSTG;
        load_chunk_h(A, W, row0, col0, kt + 2, sm + wst * STAGE_BYTES, tid);

        const uint32_t Ab = smb + stg * STAGE_BYTES;
        const uint32_t Bb = Ab + TILE_BYTES;

        // A fragments for ks=0 (resolved before mma loop starts)
        uint32_t a0c[4], a1c[4];
        ldm_x4(a0c, Ab + aoff);
        ldm_x4(a1c, Ab + aoff + 16 * RSB);

#pragma unroll
        for (int ks = 0; ks < 4; ks++) {
            // all B fragments for this ks first
            uint32_t br[4][4];
#pragma unroll
            for (int p = 0; p < 4; p++)
                ldm_x4(br[p], Bb + boff + (uint32_t)(p * 16 * RSB + ks * 32));
            // prefetch A for ks+1
            uint32_t a0n[4], a1n[4];
            if (ks < 3) {
                ldm_x4(a0n, Ab + aoff + (ks + 1) * 32);
                ldm_x4(a1n, Ab + aoff + 16 * RSB + (ks + 1) * 32);
            }
            // 16 MMAs: A pre-resolved, B issued 6 instrs ago
#pragma unroll
            for (int p = 0; p < 4; p++) {
                mma_f16(c_f[0][2*p],   a0c, br[p]);
                mma_f16(c_f[0][2*p+1], a0c, br[p] + 2);
                mma_f16(c_f[1][2*p],   a1c, br[p]);
                mma_f16(c_f[1][2*p+1], a1c, br[p] + 2);
            }
            if (ks < 3) {
#pragma unroll
                for (int j = 0; j < 4; j++) { a0c[j] = a0n[j]; a1c[j] = a1n[j]; }
            }
        }
        if (++stg == GSTG) stg = 0;
    }

#pragma unroll
    for (int ni = 0; ni < 8; ni++) {
        int col = col0 + wn * 64 + ni * 8 + lc * 2;
        float2 bb = *(const float2*)(bias + col);
#pragma unroll
        for (int mi = 0; mi < 2; mi++) {
            int r = row0 + wm * 32 + mi * 16 + gr;
            float o00 = c_f[mi][ni][0] + bb.x;
            float o01 = c_f[mi][ni][1] + bb.y;
            float o10 = c_f[mi][ni][2] + bb.x;
            float o11 = c_f[mi][ni][3] + bb.y;
            if (OUT_HALF) {
                __half* Ch = (__half*)C;
                *(uint32_t*)(Ch + (size_t)r * D_ + col)       = packh2(o00, o01);
                *(uint32_t*)(Ch + (size_t)(r + 8) * D_ + col) = packh2(o10, o11);
            } else {
                float* Cf = (float*)C;
                *(float2*)(Cf + (size_t)r * D_ + col)       = make_float2(o00, o01);
                *(float2*)(Cf + (size_t)(r + 8) * D_ + col) = make_float2(o10, o11);
            }
        }
    }
}

__global__ __launch_bounds__(256, 2)
void gemm_qkv_kernel(const __half* __restrict__ A,
                     const __half* __restrict__ W3,
                     const float* __restrict__ bq,
                     const float* __restrict__ bk,
                     const float* __restrict__ bv,
                     __half* __restrict__ Cq,
                     __half* __restrict__ Ck,
                     __half* __restrict__ Cv)
{
    extern __shared__ char smraw[];
    const int sel  = blockIdx.x >> 3;
    const int col0 = (blockIdx.x & 7) * TN;
    const int row0 = blockIdx.y * TM;
    const __half* W = W3 + (size_t)sel * D_ * D_;
    const float* bias = (sel == 0) ? bq : (sel == 1) ? bk : bv;
    __half* C = (sel == 0) ? Cq : (sel == 1) ? Ck : Cv;
    gemm_body_h<1>(A, W, bias, C, row0, col0, smraw);
}

__global__ __launch_bounds__(256, 2)
void gemm_o_kernel(const __half* __restrict__ A,
                   const __half* __restrict__ W,
                   const float* __restrict__ bias,
                   float* __restrict__ C)
{
    extern __shared__ char smraw[];
    gemm_body_h<0>(A, W, bias, C, blockIdx.y * TM, blockIdx.x * TN, smraw);
}

// ---------------------------------------------------------------------------
// Flash attention: CTA = 128 Q rows x one (b,h), 8 warps, 256 threads.
// fp16 mma + ldmatrix (all-B-first pipelining), ex2.f16x2 softmax,
// 3-stage KV ring. Smem 55296 -> 2 CTAs/SM (reg cap 128).
// ---------------------------------------------------------------------------
#define ASTG 3
#define AK_STRB 144
#define ATILE_BYTES (64*AK_STRB)
#define ASTAGE_BYTES (2*ATILE_BYTES)
#define ATTN_SMEM (ASTG*ASTAGE_BYTES)     // 55296
#define NKT (S_/64)

__device__ __forceinline__ void attn_load_kv(const __half* __restrict__ kg,
                                             const __half* __restrict__ vg,
                                             int kt, char* stage, int tid)
{
    if (kt < NKT) {
        const uint32_t kb = (uint32_t)__cvta_generic_to_shared(stage);
        const uint32_t vb = kb + ATILE_BYTES;
        const char* ksrc = (const char*)(kg + (size_t)kt * 64 * D_);
        const char* vsrc = (const char*)(vg + (size_t)kt * 64 * D_);
#pragma unroll
        for (int i = 0; i < 2; i++) {          // 512 items / 256 threads
            int idx = tid + (i << 8);
            int r = idx >> 3, c16 = idx & 7;
            cp16(kb + (uint32_t)(r * AK_STRB + c16 * 16),
                 ksrc + (size_t)r * (D_*2) + c16 * 16);
        }
#pragma unroll
        for (int i = 0; i < 2; i++) {
            int idx = tid + (i << 8);
            int r = idx >> 3, c16 = idx & 7;
            cp16(vb + (uint32_t)(r * AK_STRB + c16 * 16),
                 vsrc + (size_t)r * (D_*2) + c16 * 16);
        }
    }
    cp_commit();
}

__global__ __launch_bounds__(256, 2)
void attn_mma_kernel(const __half* __restrict__ Q,
                     const __half* __restrict__ Kg,
                     const __half* __restrict__ Vg,
                     __half* __restrict__ O)
{
    extern __shared__ char smraw[];
    const int tid  = threadIdx.x;
    const int lane = tid & 31;
    const int warp = tid >> 5;    // 0..7
    const int gr   = lane >> 2;
    const int lc   = lane & 3;

    const int q0 = blockIdx.x * 128;
    const int bh = blockIdx.y;
    const int b  = bh >> 4;
    const int h  = bh & 15;

    const __half* qg = Q  + ((size_t)(b * S_ + q0)) * D_ + h * HD_;
    const __half* kg = Kg + ((size_t)b * S_) * D_ + h * HD_;
    const __half* vg = Vg + ((size_t)b * S_) * D_ + h * HD_;

    attn_load_kv(kg, vg, 0, smraw, tid);
    attn_load_kv(kg, vg, 1, smraw + ASTAGE_BYTES, tid);

    const uint32_t koff = (uint32_t)(((lane & 7) + ((lane >> 4) << 3)) * AK_STRB
                                     + ((lane >> 3) & 1) * 16);
    const uint32_t voff = (uint32_t)(((lane & 7) + (((lane >> 3) & 1) << 3)) * AK_STRB
                                     + (lane >> 4) * 16);
    const uint32_t smb = (uint32_t)__cvta_generic_to_shared(smraw);

    // Q fragments straight from gmem (scale 2^-3 exact in fp16)
    uint32_t qf[4][4];
    {
        const __half2 sc = __floats2half2_rn(0.125f, 0.125f);
        const __half* q0p = qg + (size_t)(warp * 16 + gr) * D_;
        const __half* q1p = q0p + (size_t)8 * D_;
#pragma unroll
        for (int ks = 0; ks < 4; ks++) {
            const int k0 = ks * 16 + 2 * lc;
            __half2 h0 = __hmul2(*(const __half2*)(q0p + k0), sc);
            __half2 h1 = __hmul2(*(const __half2*)(q1p + k0), sc);
            __half2 h2 = __hmul2(*(const __half2*)(q0p + k0 + 8), sc);
            __half2 h3 = __hmul2(*(const __half2*)(q1p + k0 + 8), sc);
            qf[ks][0] = *(uint32_t*)&h0;
            qf[ks][1] = *(uint32_t*)&h1;
            qf[ks][2] = *(uint32_t*)&h2;
            qf[ks][3] = *(uint32_t*)&h3;
        }
    }

    float co[8][4];
#pragma unroll
    for (int ni = 0; ni < 8; ni++)
#pragma unroll
        for (int j = 0; j < 4; j++) co[ni][j] = 0.f;
    float m0 = -1e30f, m1 = -1e30f, l0 = 0.f, l1 = 0.f;

    const float L2E = 1.4426950408889634f;

    int stg = 0;
    for (int kt = 0; kt < NKT; kt++) {
        cp_wait<1>();
        __syncthreads();

        int wst = stg + 2; if (wst >= ASTG) wst -= ASTG;
        attn_load_kv(kg, vg, kt + 2, smraw + wst * ASTAGE_BYTES, tid);

        const uint32_t Kb = smb + stg * ASTAGE_BYTES;
        const uint32_t Vb = Kb + ATILE_BYTES;

        // --- S = (scaled Q) @ K^T : all-B-first per ks ---
        float c[8][4];
#pragma unroll
        for (int ni = 0; ni < 8; ni++)
#pragma unroll
            for (int j = 0; j < 4; j++) c[ni][j] = 0.f;

#pragma unroll
        for (int ks = 0; ks < 4; ks++) {
            uint32_t br[4][4];
#pragma unroll
            for (int p = 0; p < 4; p++)
                ldm_x4(br[p], Kb + koff + (uint32_t)(p * 16 * AK_STRB + ks * 32));
#pragma unroll
            for (int p = 0; p < 4; p++) {
                mma_f16(c[2*p],   qf[ks], br[p]);
                mma_f16(c[2*p+1], qf[ks], br[p] + 2);
            }
        }

        // --- online softmax (ex2.approx.f16x2) ---
        float mt0 = fmaxf(c[0][0], c[0][1]);
        float mt1 = fmaxf(c[0][2], c[0][3]);
#pragma unroll
        for (int ni = 1; ni < 8; ni++) {
            mt0 = fmaxf(mt0, fmaxf(c[ni][0], c[ni][1]));
            mt1 = fmaxf(mt1, fmaxf(c[ni][2], c[ni][3]));
        }
        mt0 = fmaxf(mt0, __shfl_xor_sync(0xffffffffu, mt0, 1));
        mt0 = fmaxf(mt0, __shfl_xor_sync(0xffffffffu, mt0, 2));
        mt1 = fmaxf(mt1, __shfl_xor_sync(0xffffffffu, mt1, 1));
        mt1 = fmaxf(mt1, __shfl_xor_sync(0xffffffffu, mt1, 2));

        const float mn0 = fmaxf(m0, mt0);
        const float mn1 = fmaxf(m1, mt1);
        const float al0 = __expf(m0 - mn0);
        const float al1 = __expf(m1 - mn1);
        const float bb0 = -mn0 * L2E;
        const float bb1 = -mn1 * L2E;

        uint32_t pr[8][2];
        float rs0 = 0.f, rs1 = 0.f;
#pragma unroll
        for (int ni = 0; ni < 8; ni++) {
            float e0 = fmaf(c[ni][0], L2E, bb0);
            float e1 = fmaf(c[ni][1], L2E, bb0);
            float e2 = fmaf(c[ni][2], L2E, bb1);
            float e3 = fmaf(c[ni][3], L2E, bb1);
            uint32_t p01 = ex2_h2(packh2(e0, e1));
            uint32_t p23 = ex2_h2(packh2(e2, e3));
            pr[ni][0] = p01;
            pr[ni][1] = p23;
            float2 f01 = __half22float2(*(__half2*)&p01);
            float2 f23 = __half22float2(*(__half2*)&p23);
            rs0 += f01.x + f01.y;
            rs1 += f23.x + f23.y;
        }
        rs0 += __shfl_xor_sync(0xffffffffu, rs0, 1);
        rs0 += __shfl_xor_sync(0xffffffffu, rs0, 2);
        rs1 += __shfl_xor_sync(0xffffffffu, rs1, 1);
        rs1 += __shfl_xor_sync(0xffffffffu, rs1, 2);

        l0 = l0 * al0 + rs0;  m0 = mn0;
        l1 = l1 * al1 + rs1;  m1 = mn1;

#pragma unroll
        for (int ni = 0; ni < 8; ni++) {
            co[ni][0] *= al0; co[ni][1] *= al0;
            co[ni][2] *= al1; co[ni][3] *= al1;
        }

        // --- O += P @ V : all-B-first per ks; ex2 outputs are A-frags ---
#pragma unroll
        for (int ks = 0; ks < 4; ks++) {
            uint32_t br[4][4];
#pragma unroll
            for (int p = 0; p < 4; p++)
                ldm_x4_t(br[p], Vb + voff + (uint32_t)(ks * 16 * AK_STRB + p * 32));
            uint32_t af[4];
            af[0] = pr[2*ks][0];
            af[1] = pr[2*ks][1];
            af[2] = pr[2*ks+1][0];
            af[3] = pr[2*ks+1][1];
#pragma unroll
            for (int p = 0; p < 4; p++) {
                mma_f16(co[2*p],   af, br[p]);
                mma_f16(co[2*p+1], af, br[p] + 2);
            }
        }

        if (++stg == ASTG) stg = 0;
    }

    // --- finalize ---
    const float inv0 = 1.f / l0;
    const float inv1 = 1.f / l1;
    const int n0 = b * S_ + q0 + warp * 16 + gr;
#pragma unroll
    for (int ni = 0; ni < 8; ni++) {
        const int col = h * HD_ + ni * 8 + lc * 2;
        *(uint32_t*)(O + (size_t)n0 * D_ + col) =
            packh2(co[ni][0] * inv0, co[ni][1] * inv0);
        *(uint32_t*)(O + (size_t)(n0 + 8) * D_ + col) =
            packh2(co[ni][2] * inv1, co[ni][3] * inv1);
    }
}

// ---------------------------------------------------------------------------
extern "C" void kernel_launch(void* const* d_in, const int* in_sizes, int n_in,
                              void* d_out, int out_size)
{
    const float* x  = (const float*)d_in[0];
    const float* Wq = (const float*)d_in[1];
    const float* bq = (const float*)d_in[2];
    const float* Wk = (const float*)d_in[3];
    const float* bk = (const float*)d_in[4];
    const float* Wv = (const float*)d_in[5];
    const float* bv = (const float*)d_in[6];
    const float* Wo = (const float*)d_in[7];
    const float* bo = (const float*)d_in[8];
    float* out = (float*)d_out;

    __half *xh, *wh3, *wh, *qh, *kh, *vh, *oh;
    cudaGetSymbolAddress((void**)&xh,  g_xh);
    cudaGetSymbolAddress((void**)&wh3, g_wh3);
    cudaGetSymbolAddress((void**)&wh,  g_wh);
    cudaGetSymbolAddress((void**)&qh,  g_qh);
    cudaGetSymbolAddress((void**)&kh,  g_kh);
    cudaGetSymbolAddress((void**)&vh,  g_vh);
    cudaGetSymbolAddress((void**)&oh,  g_oh);

    cudaFuncSetAttribute(gemm_qkv_kernel,
                         cudaFuncAttributeMaxDynamicSharedMemorySize, GEMM_SMEM);
    cudaFuncSetAttribute(gemm_o_kernel,
                         cudaFuncAttributeMaxDynamicSharedMemorySize, GEMM_SMEM);
    cudaFuncSetAttribute(attn_mma_kernel,
                         cudaFuncAttributeMaxDynamicSharedMemorySize, ATTN_SMEM);

    const int ntot4 = NX4 + 4 * NW4;
    cvt_all_kernel<<<ntot4 / 256, 256>>>(x, Wq, Wk, Wv, Wo, xh, wh3, wh);

    gemm_qkv_kernel<<<dim3(24, N_ / TM), 256, GEMM_SMEM>>>(
        xh, wh3, bq, bk, bv, qh, kh, vh);

    attn_mma_kernel<<<dim3(S_ / 128, B_ * H_), 256, ATTN_SMEM>>>(qh, kh, vh, oh);

    gemm_o_kernel<<<dim3(D_ / TN, N_ / TM), 256, GEMM_SMEM>>>(oh, wh, bo, out);
}

// round 13
// speedup vs baseline: 1.0087x; 1.0087x over previous
#include <cuda_runtime.h>
#include <cuda_fp16.h>
#include <stdint.h>

#define B_  2
#define S_  2048
#define D_  1024
#define H_  16
#define HD_ 64
#define N_  (B_*S_)   // 4096

// Scratch (allocation-free rule: __device__ globals)
__device__ __half g_xh[N_*D_];
__device__ __half g_wh3[3*D_*D_];
__device__ __half g_wh[D_*D_];
__device__ __half g_qh[N_*D_];
__device__ __half g_kh[N_*D_];
__device__ __half g_vh[N_*D_];
__device__ __half g_oh[N_*D_];

// ---------------------------------------------------------------------------
// Base-PTX helpers
// ---------------------------------------------------------------------------
__device__ __forceinline__ void cp16(uint32_t dst, const void* src) {
    asm volatile("cp.async.cg.shared.global [%0], [%1], 16;"
                 :: "r"(dst), "l"(__cvta_generic_to_global(src)));
}
__device__ __forceinline__ void cp_commit() {
    asm volatile("cp.async.commit_group;");
}
template<int N> __device__ __forceinline__ void cp_wait() {
    asm volatile("cp.async.wait_group %0;" :: "n"(N));
}
__device__ __forceinline__ void mma_f16(float c[4],
                                        const uint32_t a[4],
                                        const uint32_t b[2]) {
    asm volatile(
        "mma.sync.aligned.m16n8k16.row.col.f32.f16.f16.f32 "
        "{%0,%1,%2,%3}, {%4,%5,%6,%7}, {%8,%9}, {%0,%1,%2,%3};"
        : "+f"(c[0]), "+f"(c[1]), "+f"(c[2]), "+f"(c[3])
        : "r"(a[0]), "r"(a[1]), "r"(a[2]), "r"(a[3]),
          "r"(b[0]), "r"(b[1]));
}
__device__ __forceinline__ void ldm_x4(uint32_t r[4], uint32_t a) {
    asm volatile("ldmatrix.sync.aligned.m8n8.x4.shared.b16 {%0,%1,%2,%3}, [%4];"
                 : "=r"(r[0]), "=r"(r[1]), "=r"(r[2]), "=r"(r[3]) : "r"(a));
}
__device__ __forceinline__ void ldm_x4_t(uint32_t r[4], uint32_t a) {
    asm volatile("ldmatrix.sync.aligned.m8n8.x4.trans.shared.b16 {%0,%1,%2,%3}, [%4];"
                 : "=r"(r[0]), "=r"(r[1]), "=r"(r[2]), "=r"(r[3]) : "r"(a));
}
__device__ __forceinline__ uint32_t packh2(float x, float y) {
    __half2 h = __floats2half2_rn(x, y);
    return *(uint32_t*)&h;
}
__device__ __forceinline__ uint32_t ex2_h2(uint32_t h) {
    uint32_t r;
    asm("ex2.approx.f16x2 %0, %1;" : "=r"(r) : "r"(h));
    return r;
}

// ---------------------------------------------------------------------------
// Fused prepass: convert x, Wq, Wk, Wv, Wo fp32 -> fp16 in ONE launch
// ---------------------------------------------------------------------------
#define NX4 (N_*D_/4)
#define NW4 (D_*D_/4)

__global__ __launch_bounds__(256)
void cvt_all_kernel(const float* __restrict__ x,
                    const float* __restrict__ Wq,
                    const float* __restrict__ Wk,
                    const float* __restrict__ Wv,
                    const float* __restrict__ Wo,
                    __half* __restrict__ xh,
                    __half* __restrict__ wh3,
                    __half* __restrict__ wh)
{
    int i = blockIdx.x * blockDim.x + threadIdx.x;
    const float* src; __half* dst; int off;
    if (i < NX4)              { src = x;  dst = xh;                     off = i; }
    else if (i < NX4 + NW4)   { src = Wq; dst = wh3;                    off = i - NX4; }
    else if (i < NX4 + 2*NW4) { src = Wk; dst = wh3 + (size_t)D_*D_;    off = i - NX4 - NW4; }
    else if (i < NX4 + 3*NW4) { src = Wv; dst = wh3 + (size_t)2*D_*D_;  off = i - NX4 - 2*NW4; }
    else                      { src = Wo; dst = wh;                     off = i - NX4 - 3*NW4; }
    float4 v = ((const float4*)src)[off];
    uint2 o;
    o.x = packh2(v.x, v.y);
    o.y = packh2(v.z, v.w);
    ((uint2*)dst)[off] = o;
}

// ---------------------------------------------------------------------------
// fp16 tensor-core GEMM (round-11 proven version): K chunk 64 halves,
// 3-stage ring, one barrier per chunk, interleaved ldmatrix fragments.
// ---------------------------------------------------------------------------
#define TM 128
#define TN 128
#define KCH 64
#define NCH (D_/KCH)                // 16
#define GSTG 3
#define RSB 144
#define TILE_BYTES (128*RSB)        // 18432
#define STAGE_BYTES (2*TILE_BYTES)  // 36864
#define GEMM_SMEM (GSTG*STAGE_BYTES) // 110592

__device__ __forceinline__ void load_chunk_h(const __half* __restrict__ A,
                                             const __half* __restrict__ W,
                                             int row0, int col0, int c,
                                             char* stage, int tid)
{
    if (c < NCH) {
        const uint32_t abase = (uint32_t)__cvta_generic_to_shared(stage);
        const uint32_t bbase = abase + TILE_BYTES;
        const char* asrc = (const char*)(A + (size_t)row0 * D_ + c * KCH);
        const char* bsrc = (const char*)(W + (size_t)col0 * D_ + c * KCH);
#pragma unroll
        for (int i = 0; i < 4; i++) {
            int idx = tid + (i << 8);
            int r = idx >> 3, c16 = idx & 7;
            cp16(abase + (uint32_t)(r * RSB + c16 * 16),
                 asrc + (size_t)r * (D_*2) + c16 * 16);
        }
#pragma unroll
        for (int i = 0; i < 4; i++) {
            int idx = tid + (i << 8);
            int r = idx >> 3, c16 = idx & 7;
            cp16(bbase + (uint32_t)(r * RSB + c16 * 16),
                 bsrc + (size_t)r * (D_*2) + c16 * 16);
        }
    }
    cp_commit();
}

template<int OUT_HALF>
__device__ __forceinline__ void gemm_body_h(const __half* __restrict__ A,
                                            const __half* __restrict__ W,
                                            const float* __restrict__ bias,
                                            void* __restrict__ C,
                                            int row0, int col0, char* sm)
{
    const int tid  = threadIdx.x;
    const int lane = tid & 31;
    const int warp = tid >> 5;
    const int wm   = warp & 3;
    const int wn   = warp >> 2;
    const int gr = lane >> 2;
    const int lc = lane & 3;

    const uint32_t aoff = (uint32_t)((wm * 32 + (lane & 15)) * RSB + (lane >> 4) * 16);
    const uint32_t boff = (uint32_t)((wn * 64 + (lane & 7) + ((lane >> 4) << 3)) * RSB
                                     + ((lane >> 3) & 1) * 16);
    const uint32_t smb = (uint32_t)__cvta_generic_to_shared(sm);

    float c_f[2][8][4];
#pragma unroll
    for (int mi = 0; mi < 2; mi++)
#pragma unroll
        for (int ni = 0; ni < 8; ni++)
#pragma unroll
            for (int j = 0; j < 4; j++) c_f[mi][ni][j] = 0.f;

    load_chunk_h(A, W, row0, col0, 0, sm, tid);
    load_chunk_h(A, W, row0, col0, 1, sm + STAGE_BYTES, tid);

    int stg = 0;
    for (int kt = 0; kt < NCH; kt++) {
        cp_wait<GSTG - 2>();
        __syncthreads();

        int wst = stg + 2; if (wst >= GSTG) wst -= GSTG;
        load_chunk_h(A, W, row0, col0, kt + 2, sm + wst * STAGE_BYTES, tid);

        const uint32_t Ab = smb + stg * STAGE_BYTES;
        const uint32_t Bb = Ab + TILE_BYTES;

#pragma unroll
        for (int ks = 0; ks < 4; ks++) {       // 4 x k16 per 64-half chunk
            uint32_t a0[4], a1[4];
            ldm_x4(a0, Ab + aoff + ks * 32);
            ldm_x4(a1, Ab + aoff + 16 * RSB + ks * 32);
#pragma unroll
            for (int p = 0; p < 4; p++) {
                uint32_t br[4];
                ldm_x4(br, Bb + boff + (uint32_t)(p * 16 * RSB + ks * 32));
                mma_f16(c_f[0][2*p],   a0, br);
                mma_f16(c_f[0][2*p+1], a0, br + 2);
                mma_f16(c_f[1][2*p],   a1, br);
                mma_f16(c_f[1][2*p+1], a1, br + 2);
            }
        }
        if (++stg == GSTG) stg = 0;
    }

#pragma unroll
    for (int ni = 0; ni < 8; ni++) {
        int col = col0 + wn * 64 + ni * 8 + lc * 2;
        float2 bb = *(const float2*)(bias + col);
#pragma unroll
        for (int mi = 0; mi < 2; mi++) {
            int r = row0 + wm * 32 + mi * 16 + gr;
            float o00 = c_f[mi][ni][0] + bb.x;
            float o01 = c_f[mi][ni][1] + bb.y;
            float o10 = c_f[mi][ni][2] + bb.x;
            float o11 = c_f[mi][ni][3] + bb.y;
            if (OUT_HALF) {
                __half* Ch = (__half*)C;
                *(uint32_t*)(Ch + (size_t)r * D_ + col)       = packh2(o00, o01);
                *(uint32_t*)(Ch + (size_t)(r + 8) * D_ + col) = packh2(o10, o11);
            } else {
                float* Cf = (float*)C;
                *(float2*)(Cf + (size_t)r * D_ + col)       = make_float2(o00, o01);
                *(float2*)(Cf + (size_t)(r + 8) * D_ + col) = make_float2(o10, o11);
            }
        }
    }
}

__global__ __launch_bounds__(256, 2)
void gemm_qkv_kernel(const __half* __restrict__ A,
                     const __half* __restrict__ W3,
                     const float* __restrict__ bq,
                     const float* __restrict__ bk,
                     const float* __restrict__ bv,
                     __half* __restrict__ Cq,
                     __half* __restrict__ Ck,
                     __half* __restrict__ Cv)
{
    extern __shared__ char smraw[];
    const int sel  = blockIdx.x >> 3;
    const int col0 = (blockIdx.x & 7) * TN;
    const int row0 = blockIdx.y * TM;
    const __half* W = W3 + (size_t)sel * D_ * D_;
    const float* bias = (sel == 0) ? bq : (sel == 1) ? bk : bv;
    __half* C = (sel == 0) ? Cq : (sel == 1) ? Ck : Cv;
    gemm_body_h<1>(A, W, bias, C, row0, col0, smraw);
}

__global__ __launch_bounds__(256, 2)
void gemm_o_kernel(const __half* __restrict__ A,
                   const __half* __restrict__ W,
                   const float* __restrict__ bias,
                   float* __restrict__ C)
{
    extern __shared__ char smraw[];
    gemm_body_h<0>(A, W, bias, C, blockIdx.y * TM, blockIdx.x * TN, smraw);
}

// ---------------------------------------------------------------------------
// Flash attention: CTA = 128 Q rows x one (b,h), 8 warps, 256 threads.
// Round-11 interleaved inner loops (no register-pressure spike), 3-stage
// KV ring, ex2.f16x2 softmax. KV L2 traffic halved vs 64-row CTA.
// Smem 55296 -> 2 CTAs/SM (16 warps/SM, same as round 11).
// ---------------------------------------------------------------------------
#define ASTG 3
#define AK_STRB 144
#define ATILE_BYTES (64*AK_STRB)
#define ASTAGE_BYTES (2*ATILE_BYTES)
#define ATTN_SMEM (ASTG*ASTAGE_BYTES)     // 55296
#define NKT (S_/64)

__device__ __forceinline__ void attn_load_kv(const __half* __restrict__ kg,
                                             const __half* __restrict__ vg,
                                             int kt, char* stage, int tid)
{
    if (kt < NKT) {
        const uint32_t kb = (uint32_t)__cvta_generic_to_shared(stage);
        const uint32_t vb = kb + ATILE_BYTES;
        const char* ksrc = (const char*)(kg + (size_t)kt * 64 * D_);
        const char* vsrc = (const char*)(vg + (size_t)kt * 64 * D_);
#pragma unroll
        for (int i = 0; i < 2; i++) {          // 512 cp16 over 256 threads
            int idx = tid + (i << 8);
            int r = idx >> 3, c16 = idx & 7;
            cp16(kb + (uint32_t)(r * AK_STRB + c16 * 16),
                 ksrc + (size_t)r * (D_*2) + c16 * 16);
        }
#pragma unroll
        for (int i = 0; i < 2; i++) {
            int idx = tid + (i << 8);
            int r = idx >> 3, c16 = idx & 7;
            cp16(vb + (uint32_t)(r * AK_STRB + c16 * 16),
                 vsrc + (size_t)r * (D_*2) + c16 * 16);
        }
    }
    cp_commit();
}

__global__ __launch_bounds__(256, 2)
void attn_mma_kernel(const __half* __restrict__ Q,
                     const __half* __restrict__ Kg,
                     const __half* __restrict__ Vg,
                     __half* __restrict__ O)
{
    extern __shared__ char smraw[];
    const int tid  = threadIdx.x;
    const int lane = tid & 31;
    const int warp = tid >> 5;    // 0..7 -> Q rows warp*16..warp*16+15 (+8 pairs)
    const int gr   = lane >> 2;
    const int lc   = lane & 3;

    const int q0 = blockIdx.x * 128;
    const int bh = blockIdx.y;
    const int b  = bh >> 4;
    const int h  = bh & 15;

    const __half* qg = Q  + ((size_t)(b * S_ + q0)) * D_ + h * HD_;
    const __half* kg = Kg + ((size_t)b * S_) * D_ + h * HD_;
    const __half* vg = Vg + ((size_t)b * S_) * D_ + h * HD_;

    attn_load_kv(kg, vg, 0, smraw, tid);
    attn_load_kv(kg, vg, 1, smraw + ASTAGE_BYTES, tid);

    const uint32_t koff = (uint32_t)(((lane & 7) + ((lane >> 4) << 3)) * AK_STRB
                                     + ((lane >> 3) & 1) * 16);
    const uint32_t voff = (uint32_t)(((lane & 7) + (((lane >> 3) & 1) << 3)) * AK_STRB
                                     + (lane >> 4) * 16);
    const uint32_t smb = (uint32_t)__cvta_generic_to_shared(smraw);

    // Q fragments straight from gmem (scale 2^-3 exact in fp16)
    uint32_t qf[4][4];
    {
        const __half2 sc = __floats2half2_rn(0.125f, 0.125f);
        const __half* q0p = qg + (size_t)(warp * 16 + gr) * D_;
        const __half* q1p = q0p + (size_t)8 * D_;
#pragma unroll
        for (int ks = 0; ks < 4; ks++) {
            const int k0 = ks * 16 + 2 * lc;
            __half2 h0 = __hmul2(*(const __half2*)(q0p + k0), sc);
            __half2 h1 = __hmul2(*(const __half2*)(q1p + k0), sc);
            __half2 h2 = __hmul2(*(const __half2*)(q0p + k0 + 8), sc);
            __half2 h3 = __hmul2(*(const __half2*)(q1p + k0 + 8), sc);
            qf[ks][0] = *(uint32_t*)&h0;
            qf[ks][1] = *(uint32_t*)&h1;
            qf[ks][2] = *(uint32_t*)&h2;
            qf[ks][3] = *(uint32_t*)&h3;
        }
    }

    float co[8][4];
#pragma unroll
    for (int ni = 0; ni < 8; ni++)
#pragma unroll
        for (int j = 0; j < 4; j++) co[ni][j] = 0.f;
    float m0 = -1e30f, m1 = -1e30f, l0 = 0.f, l1 = 0.f;

    const float L2E = 1.4426950408889634f;

    int stg = 0;
    for (int kt = 0; kt < NKT; kt++) {
        cp_wait<1>();
        __syncthreads();

        int wst = stg + 2; if (wst >= ASTG) wst -= ASTG;
        attn_load_kv(kg, vg, kt + 2, smraw + wst * ASTAGE_BYTES, tid);

        const uint32_t Kb = smb + stg * ASTAGE_BYTES;
        const uint32_t Vb = Kb + ATILE_BYTES;

        // --- S = (scaled Q) @ K^T (interleaved, round-11 style) ---
        float c[8][4];
#pragma unroll
        for (int ni = 0; ni < 8; ni++)
#pragma unroll
            for (int j = 0; j < 4; j++) c[ni][j] = 0.f;

#pragma unroll
        for (int ks = 0; ks < 4; ks++) {
#pragma unroll
            for (int p = 0; p < 4; p++) {
                uint32_t br[4];
                ldm_x4(br, Kb + koff + (uint32_t)(p * 16 * AK_STRB + ks * 32));
                mma_f16(c[2*p],   qf[ks], br);
                mma_f16(c[2*p+1], qf[ks], br + 2);
            }
        }

        // --- online softmax (ex2.approx.f16x2) ---
        float mt0 = fmaxf(c[0][0], c[0][1]);
        float mt1 = fmaxf(c[0][2], c[0][3]);
#pragma unroll
        for (int ni = 1; ni < 8; ni++) {
            mt0 = fmaxf(mt0, fmaxf(c[ni][0], c[ni][1]));
            mt1 = fmaxf(mt1, fmaxf(c[ni][2], c[ni][3]));
        }
        mt0 = fmaxf(mt0, __shfl_xor_sync(0xffffffffu, mt0, 1));
        mt0 = fmaxf(mt0, __shfl_xor_sync(0xffffffffu, mt0, 2));
        mt1 = fmaxf(mt1, __shfl_xor_sync(0xffffffffu, mt1, 1));
        mt1 = fmaxf(mt1, __shfl_xor_sync(0xffffffffu, mt1, 2));

        const float mn0 = fmaxf(m0, mt0);
        const float mn1 = fmaxf(m1, mt1);
        const float al0 = __expf(m0 - mn0);
        const float al1 = __expf(m1 - mn1);
        const float bb0 = -mn0 * L2E;
        const float bb1 = -mn1 * L2E;

        uint32_t pr[8][2];
        float rs0 = 0.f, rs1 = 0.f;
#pragma unroll
        for (int ni = 0; ni < 8; ni++) {
            float e0 = fmaf(c[ni][0], L2E, bb0);
            float e1 = fmaf(c[ni][1], L2E, bb0);
            float e2 = fmaf(c[ni][2], L2E, bb1);
            float e3 = fmaf(c[ni][3], L2E, bb1);
            uint32_t p01 = ex2_h2(packh2(e0, e1));
            uint32_t p23 = ex2_h2(packh2(e2, e3));
            pr[ni][0] = p01;
            pr[ni][1] = p23;
            float2 f01 = __half22float2(*(__half2*)&p01);
            float2 f23 = __half22float2(*(__half2*)&p23);
            rs0 += f01.x + f01.y;
            rs1 += f23.x + f23.y;
        }
        rs0 += __shfl_xor_sync(0xffffffffu, rs0, 1);
        rs0 += __shfl_xor_sync(0xffffffffu, rs0, 2);
        rs1 += __shfl_xor_sync(0xffffffffu, rs1, 1);
        rs1 += __shfl_xor_sync(0xffffffffu, rs1, 2);

        l0 = l0 * al0 + rs0;  m0 = mn0;
        l1 = l1 * al1 + rs1;  m1 = mn1;

#pragma unroll
        for (int ni = 0; ni < 8; ni++) {
            co[ni][0] *= al0; co[ni][1] *= al0;
            co[ni][2] *= al1; co[ni][3] *= al1;
        }

        // --- O += P @ V (interleaved; ex2 outputs are A-frags) ---
#pragma unroll
        for (int ks = 0; ks < 4; ks++) {
            uint32_t af[4];
            af[0] = pr[2*ks][0];
            af[1] = pr[2*ks][1];
            af[2] = pr[2*ks+1][0];
            af[3] = pr[2*ks+1][1];
#pragma unroll
            for (int p = 0; p < 4; p++) {
                uint32_t br[4];
                ldm_x4_t(br, Vb + voff + (uint32_t)(ks * 16 * AK_STRB + p * 32));
                mma_f16(co[2*p],   af, br);
                mma_f16(co[2*p+1], af, br + 2);
            }
        }

        if (++stg == ASTG) stg = 0;
    }

    // --- finalize ---
    const float inv0 = 1.f / l0;
    const float inv1 = 1.f / l1;
    const int n0 = b * S_ + q0 + warp * 16 + gr;
#pragma unroll
    for (int ni = 0; ni < 8; ni++) {
        const int col = h * HD_ + ni * 8 + lc * 2;
        *(uint32_t*)(O + (size_t)n0 * D_ + col) =
            packh2(co[ni][0] * inv0, co[ni][1] * inv0);
        *(uint32_t*)(O + (size_t)(n0 + 8) * D_ + col) =
            packh2(co[ni][2] * inv1, co[ni][3] * inv1);
    }
}

// ---------------------------------------------------------------------------
extern "C" void kernel_launch(void* const* d_in, const int* in_sizes, int n_in,
                              void* d_out, int out_size)
{
    const float* x  = (const float*)d_in[0];
    const float* Wq = (const float*)d_in[1];
    const float* bq = (const float*)d_in[2];
    const float* Wk = (const float*)d_in[3];
    const float* bk = (const float*)d_in[4];
    const float* Wv = (const float*)d_in[5];
    const float* bv = (const float*)d_in[6];
    const float* Wo = (const float*)d_in[7];
    const float* bo = (const float*)d_in[8];
    float* out = (float*)d_out;

    __half *xh, *wh3, *wh, *qh, *kh, *vh, *oh;
    cudaGetSymbolAddress((void**)&xh,  g_xh);
    cudaGetSymbolAddress((void**)&wh3, g_wh3);
    cudaGetSymbolAddress((void**)&wh,  g_wh);
    cudaGetSymbolAddress((void**)&qh,  g_qh);
    cudaGetSymbolAddress((void**)&kh,  g_kh);
    cudaGetSymbolAddress((void**)&vh,  g_vh);
    cudaGetSymbolAddress((void**)&oh,  g_oh);

    cudaFuncSetAttribute(gemm_qkv_kernel,
                         cudaFuncAttributeMaxDynamicSharedMemorySize, GEMM_SMEM);
    cudaFuncSetAttribute(gemm_o_kernel,
                         cudaFuncAttributeMaxDynamicSharedMemorySize, GEMM_SMEM);
    cudaFuncSetAttribute(attn_mma_kernel,
                         cudaFuncAttributeMaxDynamicSharedMemorySize, ATTN_SMEM);

    const int ntot4 = NX4 + 4 * NW4;
    cvt_all_kernel<<<ntot4 / 256, 256>>>(x, Wq, Wk, Wv, Wo, xh, wh3, wh);

    gemm_qkv_kernel<<<dim3(24, N_ / TM), 256, GEMM_SMEM>>>(
        xh, wh3, bq, bk, bv, qh, kh, vh);

    attn_mma_kernel<<<dim3(S_ / 128, B_ * H_), 256, ATTN_SMEM>>>(qh, kh, vh, oh);

    gemm_o_kernel<<<dim3(D_ / TN, N_ / TM), 256, GEMM_SMEM>>>(oh, wh, bo, out);
}

// round 14
// speedup vs baseline: 1.0421x; 1.0331x over previous
#include <cuda_runtime.h>
#include <cuda_fp16.h>
#include <stdint.h>

#define B_  2
#define S_  2048
#define D_  1024
#define H_  16
#define HD_ 64
#define N_  (B_*S_)   // 4096

// Scratch (allocation-free rule: __device__ globals)
__device__ __half g_xh[N_*D_];
__device__ __half g_wh3[3*D_*D_];
__device__ __half g_wh[D_*D_];
__device__ __half g_qh[N_*D_];
__device__ __half g_kh[N_*D_];
__device__ __half g_vh[N_*D_];
__device__ __half g_oh[N_*D_];

// ---------------------------------------------------------------------------
// Base-PTX helpers
// ---------------------------------------------------------------------------
__device__ __forceinline__ void cp16(uint32_t dst, const void* src) {
    asm volatile("cp.async.cg.shared.global [%0], [%1], 16;"
                 :: "r"(dst), "l"(__cvta_generic_to_global(src)));
}
__device__ __forceinline__ void cp_commit() {
    asm volatile("cp.async.commit_group;");
}
template<int N> __device__ __forceinline__ void cp_wait() {
    asm volatile("cp.async.wait_group %0;" :: "n"(N));
}
__device__ __forceinline__ void mma_f16(float c[4],
                                        const uint32_t a[4],
                                        const uint32_t b[2]) {
    asm volatile(
        "mma.sync.aligned.m16n8k16.row.col.f32.f16.f16.f32 "
        "{%0,%1,%2,%3}, {%4,%5,%6,%7}, {%8,%9}, {%0,%1,%2,%3};"
        : "+f"(c[0]), "+f"(c[1]), "+f"(c[2]), "+f"(c[3])
        : "r"(a[0]), "r"(a[1]), "r"(a[2]), "r"(a[3]),
          "r"(b[0]), "r"(b[1]));
}
__device__ __forceinline__ void ldm_x4(uint32_t r[4], uint32_t a) {
    asm volatile("ldmatrix.sync.aligned.m8n8.x4.shared.b16 {%0,%1,%2,%3}, [%4];"
                 : "=r"(r[0]), "=r"(r[1]), "=r"(r[2]), "=r"(r[3]) : "r"(a));
}
__device__ __forceinline__ void ldm_x4_t(uint32_t r[4], uint32_t a) {
    asm volatile("ldmatrix.sync.aligned.m8n8.x4.trans.shared.b16 {%0,%1,%2,%3}, [%4];"
                 : "=r"(r[0]), "=r"(r[1]), "=r"(r[2]), "=r"(r[3]) : "r"(a));
}
__device__ __forceinline__ uint32_t packh2(float x, float y) {
    __half2 h = __floats2half2_rn(x, y);
    return *(uint32_t*)&h;
}
__device__ __forceinline__ uint32_t ex2_h2(uint32_t h) {
    uint32_t r;
    asm("ex2.approx.f16x2 %0, %1;" : "=r"(r) : "r"(h));
    return r;
}

// ---------------------------------------------------------------------------
// Fused prepass: convert x, Wq, Wk, Wv, Wo fp32 -> fp16 in ONE launch
// ---------------------------------------------------------------------------
#define NX4 (N_*D_/4)
#define NW4 (D_*D_/4)

__global__ __launch_bounds__(256)
void cvt_all_kernel(const float* __restrict__ x,
                    const float* __restrict__ Wq,
                    const float* __restrict__ Wk,
                    const float* __restrict__ Wv,
                    const float* __restrict__ Wo,
                    __half* __restrict__ xh,
                    __half* __restrict__ wh3,
                    __half* __restrict__ wh)
{
    int i = blockIdx.x * blockDim.x + threadIdx.x;
    const float* src; __half* dst; int off;
    if (i < NX4)              { src = x;  dst = xh;                     off = i; }
    else if (i < NX4 + NW4)   { src = Wq; dst = wh3;                    off = i - NX4; }
    else if (i < NX4 + 2*NW4) { src = Wk; dst = wh3 + (size_t)D_*D_;    off = i - NX4 - NW4; }
    else if (i < NX4 + 3*NW4) { src = Wv; dst = wh3 + (size_t)2*D_*D_;  off = i - NX4 - 2*NW4; }
    else                      { src = Wo; dst = wh;                     off = i - NX4 - 3*NW4; }
    float4 v = ((const float4*)src)[off];
    uint2 o;
    o.x = packh2(v.x, v.y);
    o.y = packh2(v.z, v.w);
    ((uint2*)dst)[off] = o;
}

// ---------------------------------------------------------------------------
// fp16 tensor-core GEMM: big-tile 1-CTA/SM variant.
// CTA tile 256x128, 8 warps (4m x 2n), warp tile 64x64.
// K chunk 64 halves, 3-stage ring. MMA:LDSM = 32:8 per k16 step.
// ---------------------------------------------------------------------------
#define TM 256
#define TN 128
#define KCH 64
#define NCH (D_/KCH)                 // 16
#define GSTG 3
#define RSB 144
#define A_TILE_BYTES (256*RSB)       // 36864
#define B_TILE_BYTES (128*RSB)       // 18432
#define STAGE_BYTES (A_TILE_BYTES+B_TILE_BYTES)   // 55296
#define GEMM_SMEM (GSTG*STAGE_BYTES) // 165888

__device__ __forceinline__ void load_chunk_h(const __half* __restrict__ A,
                                             const __half* __restrict__ W,
                                             int row0, int col0, int c,
                                             char* stage, int tid)
{
    if (c < NCH) {
        const uint32_t abase = (uint32_t)__cvta_generic_to_shared(stage);
        const uint32_t bbase = abase + A_TILE_BYTES;
        const char* asrc = (const char*)(A + (size_t)row0 * D_ + c * KCH);
        const char* bsrc = (const char*)(W + (size_t)col0 * D_ + c * KCH);
#pragma unroll
        for (int i = 0; i < 8; i++) {          // 256 rows x 128B = 2048 cp16
            int idx = tid + (i << 8);
            int r = idx >> 3, c16 = idx & 7;
            cp16(abase + (uint32_t)(r * RSB + c16 * 16),
                 asrc + (size_t)r * (D_*2) + c16 * 16);
        }
#pragma unroll
        for (int i = 0; i < 4; i++) {          // 128 rows x 128B = 1024 cp16
            int idx = tid + (i << 8);
            int r = idx >> 3, c16 = idx & 7;
            cp16(bbase + (uint32_t)(r * RSB + c16 * 16),
                 bsrc + (size_t)r * (D_*2) + c16 * 16);
        }
    }
    cp_commit();
}

template<int OUT_HALF>
__device__ __forceinline__ void gemm_body_h(const __half* __restrict__ A,
                                            const __half* __restrict__ W,
                                            const float* __restrict__ bias,
                                            void* __restrict__ C,
                                            int row0, int col0, char* sm)
{
    const int tid  = threadIdx.x;
    const int lane = tid & 31;
    const int warp = tid >> 5;
    const int wm   = warp & 3;        // 4 m-warps (64 rows each)
    const int wn   = warp >> 2;       // 2 n-warps (64 cols each)
    const int gr = lane >> 2;
    const int lc = lane & 3;

    // ldmatrix per-thread offsets
    const uint32_t aoff = (uint32_t)((wm * 64 + (lane & 15)) * RSB + (lane >> 4) * 16);
    const uint32_t boff = (uint32_t)((wn * 64 + (lane & 7) + ((lane >> 4) << 3)) * RSB
                                     + ((lane >> 3) & 1) * 16);
    const uint32_t smb = (uint32_t)__cvta_generic_to_shared(sm);

    float c_f[4][8][4];               // 128 accumulator regs
#pragma unroll
    for (int mi = 0; mi < 4; mi++)
#pragma unroll
        for (int ni = 0; ni < 8; ni++)
#pragma unroll
            for (int j = 0; j < 4; j++) c_f[mi][ni][j] = 0.f;

    load_chunk_h(A, W, row0, col0, 0, sm, tid);
    load_chunk_h(A, W, row0, col0, 1, sm + STAGE_BYTES, tid);

    int stg = 0;
    for (int kt = 0; kt < NCH; kt++) {
        cp_wait<GSTG - 2>();
        __syncthreads();

        int wst = stg + 2; if (wst >= GSTG) wst -= GSTG;
        load_chunk_h(A, W, row0, col0, kt + 2, sm + wst * STAGE_BYTES, tid);

        const uint32_t Ab = smb + stg * STAGE_BYTES;
        const uint32_t Bb = Ab + A_TILE_BYTES;

#pragma unroll
        for (int ks = 0; ks < 4; ks++) {       // 4 x k16 per 64-half chunk
            uint32_t af[4][4];
#pragma unroll
            for (int mi = 0; mi < 4; mi++)
                ldm_x4(af[mi], Ab + aoff + (uint32_t)(mi * 16 * RSB + ks * 32));
#pragma unroll
            for (int p = 0; p < 4; p++) {      // 4 n16 groups
                uint32_t br[4];
                ldm_x4(br, Bb + boff + (uint32_t)(p * 16 * RSB + ks * 32));
#pragma unroll
                for (int mi = 0; mi < 4; mi++) {
                    mma_f16(c_f[mi][2*p],   af[mi], br);
                    mma_f16(c_f[mi][2*p+1], af[mi], br + 2);
                }
            }
        }
        if (++stg == GSTG) stg = 0;
    }

#pragma unroll
    for (int ni = 0; ni < 8; ni++) {
        int col = col0 + wn * 64 + ni * 8 + lc * 2;
        float2 bb = *(const float2*)(bias + col);
#pragma unroll
        for (int mi = 0; mi < 4; mi++) {
            int r = row0 + wm * 64 + mi * 16 + gr;
            float o00 = c_f[mi][ni][0] + bb.x;
            float o01 = c_f[mi][ni][1] + bb.y;
            float o10 = c_f[mi][ni][2] + bb.x;
            float o11 = c_f[mi][ni][3] + bb.y;
            if (OUT_HALF) {
                __half* Ch = (__half*)C;
                *(uint32_t*)(Ch + (size_t)r * D_ + col)       = packh2(o00, o01);
                *(uint32_t*)(Ch + (size_t)(r + 8) * D_ + col) = packh2(o10, o11);
            } else {
                float* Cf = (float*)C;
                *(float2*)(Cf + (size_t)r * D_ + col)       = make_float2(o00, o01);
                *(float2*)(Cf + (size_t)(r + 8) * D_ + col) = make_float2(o10, o11);
            }
        }
    }
}

__global__ __launch_bounds__(256, 1)
void gemm_qkv_kernel(const __half* __restrict__ A,
                     const __half* __restrict__ W3,
                     const float* __restrict__ bq,
                     const float* __restrict__ bk,
                     const float* __restrict__ bv,
                     __half* __restrict__ Cq,
                     __half* __restrict__ Ck,
                     __half* __restrict__ Cv)
{
    extern __shared__ char smraw[];
    const int sel  = blockIdx.x >> 3;          // 8 col-blocks of 128 per matrix
    const int col0 = (blockIdx.x & 7) * TN;
    const int row0 = blockIdx.y * TM;
    const __half* W = W3 + (size_t)sel * D_ * D_;
    const float* bias = (sel == 0) ? bq : (sel == 1) ? bk : bv;
    __half* C = (sel == 0) ? Cq : (sel == 1) ? Ck : Cv;
    gemm_body_h<1>(A, W, bias, C, row0, col0, smraw);
}

__global__ __launch_bounds__(256, 1)
void gemm_o_kernel(const __half* __restrict__ A,
                   const __half* __restrict__ W,
                   const float* __restrict__ bias,
                   float* __restrict__ C)
{
    extern __shared__ char smraw[];
    gemm_body_h<0>(A, W, bias, C, blockIdx.y * TM, blockIdx.x * TN, smraw);
}

// ---------------------------------------------------------------------------
// Flash attention — round-11 version verbatim (proven optimum):
// CTA = 64 Q rows x one (b,h), 4 warps, 3-stage KV ring, ex2.f16x2 softmax,
// smem 55296 -> 4 CTAs/SM.
// ---------------------------------------------------------------------------
#define ASTG 3
#define AK_STRB 144
#define ATILE_BYTES (64*AK_STRB)
#define ASTAGE_BYTES (2*ATILE_BYTES)
#define ATTN_SMEM (ASTG*ASTAGE_BYTES)     // 55296
#define NKT (S_/64)

__device__ __forceinline__ void attn_load_kv(const __half* __restrict__ kg,
                                             const __half* __restrict__ vg,
                                             int kt, char* stage, int tid)
{
    if (kt < NKT) {
        const uint32_t kb = (uint32_t)__cvta_generic_to_shared(stage);
        const uint32_t vb = kb + ATILE_BYTES;
        const char* ksrc = (const char*)(kg + (size_t)kt * 64 * D_);
        const char* vsrc = (const char*)(vg + (size_t)kt * 64 * D_);
#pragma unroll
        for (int i = 0; i < 4; i++) {
            int idx = tid + (i << 7);
            int r = idx >> 3, c16 = idx & 7;
            cp16(kb + (uint32_t)(r * AK_STRB + c16 * 16),
                 ksrc + (size_t)r * (D_*2) + c16 * 16);
        }
#pragma unroll
        for (int i = 0; i < 4; i++) {
            int idx = tid + (i << 7);
            int r = idx >> 3, c16 = idx & 7;
            cp16(vb + (uint32_t)(r * AK_STRB + c16 * 16),
                 vsrc + (size_t)r * (D_*2) + c16 * 16);
        }
    }
    cp_commit();
}

__global__ __launch_bounds__(128, 4)
void attn_mma_kernel(const __half* __restrict__ Q,
                     const __half* __restrict__ Kg,
                     const __half* __restrict__ Vg,
                     __half* __restrict__ O)
{
    extern __shared__ char smraw[];
    const int tid  = threadIdx.x;
    const int lane = tid & 31;
    const int warp = tid >> 5;
    const int gr   = lane >> 2;
    const int lc   = lane & 3;

    const int q0 = blockIdx.x * 64;
    const int bh = blockIdx.y;
    const int b  = bh >> 4;
    const int h  = bh & 15;

    const __half* qg = Q  + ((size_t)(b * S_ + q0)) * D_ + h * HD_;
    const __half* kg = Kg + ((size_t)b * S_) * D_ + h * HD_;
    const __half* vg = Vg + ((size_t)b * S_) * D_ + h * HD_;

    attn_load_kv(kg, vg, 0, smraw, tid);
    attn_load_kv(kg, vg, 1, smraw + ASTAGE_BYTES, tid);

    const uint32_t koff = (uint32_t)(((lane & 7) + ((lane >> 4) << 3)) * AK_STRB
                                     + ((lane >> 3) & 1) * 16);
    const uint32_t voff = (uint32_t)(((lane & 7) + (((lane >> 3) & 1) << 3)) * AK_STRB
                                     + (lane >> 4) * 16);
    const uint32_t smb = (uint32_t)__cvta_generic_to_shared(smraw);

    uint32_t qf[4][4];
    {
        const __half2 sc = __floats2half2_rn(0.125f, 0.125f);
        const __half* q0p = qg + (size_t)(warp * 16 + gr) * D_;
        const __half* q1p = q0p + (size_t)8 * D_;
#pragma unroll
        for (int ks = 0; ks < 4; ks++) {
            const int k0 = ks * 16 + 2 * lc;
            __half2 h0 = __hmul2(*(const __half2*)(q0p + k0), sc);
            __half2 h1 = __hmul2(*(const __half2*)(q1p + k0), sc);
            __half2 h2 = __hmul2(*(const __half2*)(q0p + k0 + 8), sc);
            __half2 h3 = __hmul2(*(const __half2*)(q1p + k0 + 8), sc);
            qf[ks][0] = *(uint32_t*)&h0;
            qf[ks][1] = *(uint32_t*)&h1;
            qf[ks][2] = *(uint32_t*)&h2;
            qf[ks][3] = *(uint32_t*)&h3;
        }
    }

    float co[8][4];
#pragma unroll
    for (int ni = 0; ni < 8; ni++)
#pragma unroll
        for (int j = 0; j < 4; j++) co[ni][j] = 0.f;
    float m0 = -1e30f, m1 = -1e30f, l0 = 0.f, l1 = 0.f;

    const float L2E = 1.4426950408889634f;

    int stg = 0;
    for (int kt = 0; kt < NKT; kt++) {
        cp_wait<1>();
        __syncthreads();

        int wst = stg + 2; if (wst >= ASTG) wst -= ASTG;
        attn_load_kv(kg, vg, kt + 2, smraw + wst * ASTAGE_BYTES, tid);

        const uint32_t Kb = smb + stg * ASTAGE_BYTES;
        const uint32_t Vb = Kb + ATILE_BYTES;

        float c[8][4];
#pragma unroll
        for (int ni = 0; ni < 8; ni++)
#pragma unroll
            for (int j = 0; j < 4; j++) c[ni][j] = 0.f;

#pragma unroll
        for (int ks = 0; ks < 4; ks++) {
#pragma unroll
            for (int p = 0; p < 4; p++) {
                uint32_t br[4];
                ldm_x4(br, Kb + koff + (uint32_t)(p * 16 * AK_STRB + ks * 32));
                mma_f16(c[2*p],   qf[ks], br);
                mma_f16(c[2*p+1], qf[ks], br + 2);
            }
        }

        float mt0 = fmaxf(c[0][0], c[0][1]);
        float mt1 = fmaxf(c[0][2], c[0][3]);
#pragma unroll
        for (int ni = 1; ni < 8; ni++) {
            mt0 = fmaxf(mt0, fmaxf(c[ni][0], c[ni][1]));
            mt1 = fmaxf(mt1, fmaxf(c[ni][2], c[ni][3]));
        }
        mt0 = fmaxf(mt0, __shfl_xor_sync(0xffffffffu, mt0, 1));
        mt0 = fmaxf(mt0, __shfl_xor_sync(0xffffffffu, mt0, 2));
        mt1 = fmaxf(mt1, __shfl_xor_sync(0xffffffffu, mt1, 1));
        mt1 = fmaxf(mt1, __shfl_xor_sync(0xffffffffu, mt1, 2));

        const float mn0 = fmaxf(m0, mt0);
        const float mn1 = fmaxf(m1, mt1);
        const float al0 = __expf(m0 - mn0);
        const float al1 = __expf(m1 - mn1);
        const float bb0 = -mn0 * L2E;
        const float bb1 = -mn1 * L2E;

        uint32_t pr[8][2];
        float rs0 = 0.f, rs1 = 0.f;
#pragma unroll
        for (int ni = 0; ni < 8; ni++) {
            float e0 = fmaf(c[ni][0], L2E, bb0);
            float e1 = fmaf(c[ni][1], L2E, bb0);
            float e2 = fmaf(c[ni][2], L2E, bb1);
            float e3 = fmaf(c[ni][3], L2E, bb1);
            uint32_t p01 = ex2_h2(packh2(e0, e1));
            uint32_t p23 = ex2_h2(packh2(e2, e3));
            pr[ni][0] = p01;
            pr[ni][1] = p23;
            float2 f01 = __half22float2(*(__half2*)&p01);
            float2 f23 = __half22float2(*(__half2*)&p23);
            rs0 += f01.x + f01.y;
            rs1 += f23.x + f23.y;
        }
        rs0 += __shfl_xor_sync(0xffffffffu, rs0, 1);
        rs0 += __shfl_xor_sync(0xffffffffu, rs0, 2);
        rs1 += __shfl_xor_sync(0xffffffffu, rs1, 1);
        rs1 += __shfl_xor_sync(0xffffffffu, rs1, 2);

        l0 = l0 * al0 + rs0;  m0 = mn0;
        l1 = l1 * al1 + rs1;  m1 = mn1;

#pragma unroll
        for (int ni = 0; ni < 8; ni++) {
            co[ni][0] *= al0; co[ni][1] *= al0;
            co[ni][2] *= al1; co[ni][3] *= al1;
        }

#pragma unroll
        for (int ks = 0; ks < 4; ks++) {
            uint32_t af[4];
            af[0] = pr[2*ks][0];
            af[1] = pr[2*ks][1];
            af[2] = pr[2*ks+1][0];
            af[3] = pr[2*ks+1][1];
#pragma unroll
            for (int p = 0; p < 4; p++) {
                uint32_t br[4];
                ldm_x4_t(br, Vb + voff + (uint32_t)(ks * 16 * AK_STRB + p * 32));
                mma_f16(co[2*p],   af, br);
                mma_f16(co[2*p+1], af, br + 2);
            }
        }

        if (++stg == ASTG) stg = 0;
    }

    const float inv0 = 1.f / l0;
    const float inv1 = 1.f / l1;
    const int n0 = b * S_ + q0 + warp * 16 + gr;
#pragma unroll
    for (int ni = 0; ni < 8; ni++) {
        const int col = h * HD_ + ni * 8 + lc * 2;
        *(uint32_t*)(O + (size_t)n0 * D_ + col) =
            packh2(co[ni][0] * inv0, co[ni][1] * inv0);
        *(uint32_t*)(O + (size_t)(n0 + 8) * D_ + col) =
            packh2(co[ni][2] * inv1, co[ni][3] * inv1);
    }
}

// ---------------------------------------------------------------------------
extern "C" void kernel_launch(void* const* d_in, const int* in_sizes, int n_in,
                              void* d_out, int out_size)
{
    const float* x  = (const float*)d_in[0];
    const float* Wq = (const float*)d_in[1];
    const float* bq = (const float*)d_in[2];
    const float* Wk = (const float*)d_in[3];
    const float* bk = (const float*)d_in[4];
    const float* Wv = (const float*)d_in[5];
    const float* bv = (const float*)d_in[6];
    const float* Wo = (const float*)d_in[7];
    const float* bo = (const float*)d_in[8];
    float* out = (float*)d_out;

    __half *xh, *wh3, *wh, *qh, *kh, *vh, *oh;
    cudaGetSymbolAddress((void**)&xh,  g_xh);
    cudaGetSymbolAddress((void**)&wh3, g_wh3);
    cudaGetSymbolAddress((void**)&wh,  g_wh);
    cudaGetSymbolAddress((void**)&qh,  g_qh);
    cudaGetSymbolAddress((void**)&kh,  g_kh);
    cudaGetSymbolAddress((void**)&vh,  g_vh);
    cudaGetSymbolAddress((void**)&oh,  g_oh);

    cudaFuncSetAttribute(gemm_qkv_kernel,
                         cudaFuncAttributeMaxDynamicSharedMemorySize, GEMM_SMEM);
    cudaFuncSetAttribute(gemm_o_kernel,
                         cudaFuncAttributeMaxDynamicSharedMemorySize, GEMM_SMEM);
    cudaFuncSetAttribute(attn_mma_kernel,
                         cudaFuncAttributeMaxDynamicSharedMemorySize, ATTN_SMEM);

    const int ntot4 = NX4 + 4 * NW4;
    cvt_all_kernel<<<ntot4 / 256, 256>>>(x, Wq, Wk, Wv, Wo, xh, wh3, wh);

    gemm_qkv_kernel<<<dim3(24, N_ / TM), 256, GEMM_SMEM>>>(
        xh, wh3, bq, bk, bv, qh, kh, vh);

    attn_mma_kernel<<<dim3(S_ / 64, B_ * H_), 128, ATTN_SMEM>>>(qh, kh, vh, oh);

    gemm_o_kernel<<<dim3(D_ / TN, N_ / TM), 256, GEMM_SMEM>>>(oh, wh, bo, out);
}

// round 15
// speedup vs baseline: 1.0721x; 1.0288x over previous
#include <cuda_runtime.h>
#include <cuda_fp16.h>
#include <stdint.h>

#define B_  2
#define S_  2048
#define D_  1024
#define H_  16
#define HD_ 64
#define N_  (B_*S_)   // 4096

// Scratch (allocation-free rule: __device__ globals)
__device__ __half g_xh[N_*D_];
__device__ __half g_wh3[3*D_*D_];
__device__ __half g_wh[D_*D_];
__device__ __half g_qh[N_*D_];
__device__ __half g_kh[N_*D_];
__device__ __half g_vh[N_*D_];
__device__ __half g_oh[N_*D_];

// ---------------------------------------------------------------------------
// Base-PTX helpers
// ---------------------------------------------------------------------------
__device__ __forceinline__ void cp16(uint32_t dst, const void* src) {
    asm volatile("cp.async.cg.shared.global [%0], [%1], 16;"
                 :: "r"(dst), "l"(__cvta_generic_to_global(src)));
}
__device__ __forceinline__ void cp_commit() {
    asm volatile("cp.async.commit_group;");
}
template<int N> __device__ __forceinline__ void cp_wait() {
    asm volatile("cp.async.wait_group %0;" :: "n"(N));
}
__device__ __forceinline__ void mma_f16(float c[4],
                                        const uint32_t a[4],
                                        const uint32_t b[2]) {
    asm volatile(
        "mma.sync.aligned.m16n8k16.row.col.f32.f16.f16.f32 "
        "{%0,%1,%2,%3}, {%4,%5,%6,%7}, {%8,%9}, {%0,%1,%2,%3};"
        : "+f"(c[0]), "+f"(c[1]), "+f"(c[2]), "+f"(c[3])
        : "r"(a[0]), "r"(a[1]), "r"(a[2]), "r"(a[3]),
          "r"(b[0]), "r"(b[1]));
}
__device__ __forceinline__ void ldm_x4(uint32_t r[4], uint32_t a) {
    asm volatile("ldmatrix.sync.aligned.m8n8.x4.shared.b16 {%0,%1,%2,%3}, [%4];"
                 : "=r"(r[0]), "=r"(r[1]), "=r"(r[2]), "=r"(r[3]) : "r"(a));
}
__device__ __forceinline__ void ldm_x4_t(uint32_t r[4], uint32_t a) {
    asm volatile("ldmatrix.sync.aligned.m8n8.x4.trans.shared.b16 {%0,%1,%2,%3}, [%4];"
                 : "=r"(r[0]), "=r"(r[1]), "=r"(r[2]), "=r"(r[3]) : "r"(a));
}
__device__ __forceinline__ uint32_t packh2(float x, float y) {
    __half2 h = __floats2half2_rn(x, y);
    return *(uint32_t*)&h;
}
__device__ __forceinline__ uint32_t ex2_h2(uint32_t h) {
    uint32_t r;
    asm("ex2.approx.f16x2 %0, %1;" : "=r"(r) : "r"(h));
    return r;
}

// ---------------------------------------------------------------------------
// Fused prepass: convert x, Wq, Wk, Wv, Wo fp32 -> fp16 in ONE launch
// ---------------------------------------------------------------------------
#define NX4 (N_*D_/4)
#define NW4 (D_*D_/4)

__global__ __launch_bounds__(256)
void cvt_all_kernel(const float* __restrict__ x,
                    const float* __restrict__ Wq,
                    const float* __restrict__ Wk,
                    const float* __restrict__ Wv,
                    const float* __restrict__ Wo,
                    __half* __restrict__ xh,
                    __half* __restrict__ wh3,
                    __half* __restrict__ wh)
{
    int i = blockIdx.x * blockDim.x + threadIdx.x;
    const float* src; __half* dst; int off;
    if (i < NX4)              { src = x;  dst = xh;                     off = i; }
    else if (i < NX4 + NW4)   { src = Wq; dst = wh3;                    off = i - NX4; }
    else if (i < NX4 + 2*NW4) { src = Wk; dst = wh3 + (size_t)D_*D_;    off = i - NX4 - NW4; }
    else if (i < NX4 + 3*NW4) { src = Wv; dst = wh3 + (size_t)2*D_*D_;  off = i - NX4 - 2*NW4; }
    else                      { src = Wo; dst = wh;                     off = i - NX4 - 3*NW4; }
    float4 v = ((const float4*)src)[off];
    uint2 o;
    o.x = packh2(v.x, v.y);
    o.y = packh2(v.z, v.w);
    ((uint2*)dst)[off] = o;
}

// ---------------------------------------------------------------------------
// Shared GEMM constants
// ---------------------------------------------------------------------------
#define KCH 64
#define NCH (D_/KCH)                 // 16
#define GSTG 3
#define RSB 144

// ===== Small-tile GEMM (QKV): CTA 128x128, 2 CTAs/SM (round-11 proven) =====
#define STM 128
#define STN 128
#define S_TILE_BYTES (128*RSB)           // 18432
#define S_STAGE_BYTES (2*S_TILE_BYTES)   // 36864
#define QKV_SMEM (GSTG*S_STAGE_BYTES)    // 110592

__device__ __forceinline__ void load_chunk_s(const __half* __restrict__ A,
                                             const __half* __restrict__ W,
                                             int row0, int col0, int c,
                                             char* stage, int tid)
{
    if (c < NCH) {
        const uint32_t abase = (uint32_t)__cvta_generic_to_shared(stage);
        const uint32_t bbase = abase + S_TILE_BYTES;
        const char* asrc = (const char*)(A + (size_t)row0 * D_ + c * KCH);
        const char* bsrc = (const char*)(W + (size_t)col0 * D_ + c * KCH);
#pragma unroll
        for (int i = 0; i < 4; i++) {
            int idx = tid + (i << 8);
            int r = idx >> 3, c16 = idx & 7;
            cp16(abase + (uint32_t)(r * RSB + c16 * 16),
                 asrc + (size_t)r * (D_*2) + c16 * 16);
        }
#pragma unroll
        for (int i = 0; i < 4; i++) {
            int idx = tid + (i << 8);
            int r = idx >> 3, c16 = idx & 7;
            cp16(bbase + (uint32_t)(r * RSB + c16 * 16),
                 bsrc + (size_t)r * (D_*2) + c16 * 16);
        }
    }
    cp_commit();
}

__global__ __launch_bounds__(256, 2)
void gemm_qkv_kernel(const __half* __restrict__ A,
                     const __half* __restrict__ W3,
                     const float* __restrict__ bq,
                     const float* __restrict__ bk,
                     const float* __restrict__ bv,
                     __half* __restrict__ Cq,
                     __half* __restrict__ Ck,
                     __half* __restrict__ Cv)
{
    extern __shared__ char sm[];
    const int sel  = blockIdx.x >> 3;
    const int col0 = (blockIdx.x & 7) * STN;
    const int row0 = blockIdx.y * STM;
    const __half* W = W3 + (size_t)sel * D_ * D_;
    const float* bias = (sel == 0) ? bq : (sel == 1) ? bk : bv;
    __half* C = (sel == 0) ? Cq : (sel == 1) ? Ck : Cv;

    const int tid  = threadIdx.x;
    const int lane = tid & 31;
    const int warp = tid >> 5;
    const int wm   = warp & 3;
    const int wn   = warp >> 2;
    const int gr = lane >> 2;
    const int lc = lane & 3;

    const uint32_t aoff = (uint32_t)((wm * 32 + (lane & 15)) * RSB + (lane >> 4) * 16);
    const uint32_t boff = (uint32_t)((wn * 64 + (lane & 7) + ((lane >> 4) << 3)) * RSB
                                     + ((lane >> 3) & 1) * 16);
    const uint32_t smb = (uint32_t)__cvta_generic_to_shared(sm);

    float c_f[2][8][4];
#pragma unroll
    for (int mi = 0; mi < 2; mi++)
#pragma unroll
        for (int ni = 0; ni < 8; ni++)
#pragma unroll
            for (int j = 0; j < 4; j++) c_f[mi][ni][j] = 0.f;

    load_chunk_s(A, W, row0, col0, 0, sm, tid);
    load_chunk_s(A, W, row0, col0, 1, sm + S_STAGE_BYTES, tid);

    int stg = 0;
    for (int kt = 0; kt < NCH; kt++) {
        cp_wait<GSTG - 2>();
        __syncthreads();

        int wst = stg + 2; if (wst >= GSTG) wst -= GSTG;
        load_chunk_s(A, W, row0, col0, kt + 2, sm + wst * S_STAGE_BYTES, tid);

        const uint32_t Ab = smb + stg * S_STAGE_BYTES;
        const uint32_t Bb = Ab + S_TILE_BYTES;

#pragma unroll
        for (int ks = 0; ks < 4; ks++) {
            uint32_t a0[4], a1[4];
            ldm_x4(a0, Ab + aoff + ks * 32);
            ldm_x4(a1, Ab + aoff + 16 * RSB + ks * 32);
#pragma unroll
            for (int p = 0; p < 4; p++) {
                uint32_t br[4];
                ldm_x4(br, Bb + boff + (uint32_t)(p * 16 * RSB + ks * 32));
                mma_f16(c_f[0][2*p],   a0, br);
                mma_f16(c_f[0][2*p+1], a0, br + 2);
                mma_f16(c_f[1][2*p],   a1, br);
                mma_f16(c_f[1][2*p+1], a1, br + 2);
            }
        }
        if (++stg == GSTG) stg = 0;
    }

#pragma unroll
    for (int ni = 0; ni < 8; ni++) {
        int col = col0 + wn * 64 + ni * 8 + lc * 2;
        float2 bb = *(const float2*)(bias + col);
#pragma unroll
        for (int mi = 0; mi < 2; mi++) {
            int r = row0 + wm * 32 + mi * 16 + gr;
            *(uint32_t*)(C + (size_t)r * D_ + col) =
                packh2(c_f[mi][ni][0] + bb.x, c_f[mi][ni][1] + bb.y);
            *(uint32_t*)(C + (size_t)(r + 8) * D_ + col) =
                packh2(c_f[mi][ni][2] + bb.x, c_f[mi][ni][3] + bb.y);
        }
    }
}

// ===== Big-tile GEMM (O-projection): CTA 256x128, 1 CTA/SM, single wave =====
#define OTM 256
#define OTN 128
#define O_A_TILE_BYTES (256*RSB)                       // 36864
#define O_B_TILE_BYTES (128*RSB)                       // 18432
#define O_STAGE_BYTES (O_A_TILE_BYTES+O_B_TILE_BYTES)  // 55296
#define O_SMEM (GSTG*O_STAGE_BYTES)                    // 165888

__device__ __forceinline__ void load_chunk_o(const __half* __restrict__ A,
                                             const __half* __restrict__ W,
                                             int row0, int col0, int c,
                                             char* stage, int tid)
{
    if (c < NCH) {
        const uint32_t abase = (uint32_t)__cvta_generic_to_shared(stage);
        const uint32_t bbase = abase + O_A_TILE_BYTES;
        const char* asrc = (const char*)(A + (size_t)row0 * D_ + c * KCH);
        const char* bsrc = (const char*)(W + (size_t)col0 * D_ + c * KCH);
#pragma unroll
        for (int i = 0; i < 8; i++) {
            int idx = tid + (i << 8);
            int r = idx >> 3, c16 = idx & 7;
            cp16(abase + (uint32_t)(r * RSB + c16 * 16),
                 asrc + (size_t)r * (D_*2) + c16 * 16);
        }
#pragma unroll
        for (int i = 0; i < 4; i++) {
            int idx = tid + (i << 8);
            int r = idx >> 3, c16 = idx & 7;
            cp16(bbase + (uint32_t)(r * RSB + c16 * 16),
                 bsrc + (size_t)r * (D_*2) + c16 * 16);
        }
    }
    cp_commit();
}

__global__ __launch_bounds__(256, 1)
void gemm_o_kernel(const __half* __restrict__ A,
                   const __half* __restrict__ W,
                   const float* __restrict__ bias,
                   float* __restrict__ C)
{
    extern __shared__ char sm[];
    const int row0 = blockIdx.y * OTM;
    const int col0 = blockIdx.x * OTN;

    const int tid  = threadIdx.x;
    const int lane = tid & 31;
    const int warp = tid >> 5;
    const int wm   = warp & 3;        // 4 m-warps (64 rows each)
    const int wn   = warp >> 2;       // 2 n-warps (64 cols each)
    const int gr = lane >> 2;
    const int lc = lane & 3;

    const uint32_t aoff = (uint32_t)((wm * 64 + (lane & 15)) * RSB + (lane >> 4) * 16);
    const uint32_t boff = (uint32_t)((wn * 64 + (lane & 7) + ((lane >> 4) << 3)) * RSB
                                     + ((lane >> 3) & 1) * 16);
    const uint32_t smb = (uint32_t)__cvta_generic_to_shared(sm);

    float c_f[4][8][4];
#pragma unroll
    for (int mi = 0; mi < 4; mi++)
#pragma unroll
        for (int ni = 0; ni < 8; ni++)
#pragma unroll
            for (int j = 0; j < 4; j++) c_f[mi][ni][j] = 0.f;

    load_chunk_o(A, W, row0, col0, 0, sm, tid);
    load_chunk_o(A, W, row0, col0, 1, sm + O_STAGE_BYTES, tid);

    int stg = 0;
    for (int kt = 0; kt < NCH; kt++) {
        cp_wait<GSTG - 2>();
        __syncthreads();

        int wst = stg + 2; if (wst >= GSTG) wst -= GSTG;
        load_chunk_o(A, W, row0, col0, kt + 2, sm + wst * O_STAGE_BYTES, tid);

        const uint32_t Ab = smb + stg * O_STAGE_BYTES;
        const uint32_t Bb = Ab + O_A_TILE_BYTES;

#pragma unroll
        for (int ks = 0; ks < 4; ks++) {
            uint32_t af[4][4];
#pragma unroll
            for (int mi = 0; mi < 4; mi++)
                ldm_x4(af[mi], Ab + aoff + (uint32_t)(mi * 16 * RSB + ks * 32));
#pragma unroll
            for (int p = 0; p < 4; p++) {
                uint32_t br[4];
                ldm_x4(br, Bb + boff + (uint32_t)(p * 16 * RSB + ks * 32));
#pragma unroll
                for (int mi = 0; mi < 4; mi++) {
                    mma_f16(c_f[mi][2*p],   af[mi], br);
                    mma_f16(c_f[mi][2*p+1], af[mi], br + 2);
                }
            }
        }
        if (++stg == GSTG) stg = 0;
    }

#pragma unroll
    for (int ni = 0; ni < 8; ni++) {
        int col = col0 + wn * 64 + ni * 8 + lc * 2;
        float2 bb = *(const float2*)(bias + col);
#pragma unroll
        for (int mi = 0; mi < 4; mi++) {
            int r = row0 + wm * 64 + mi * 16 + gr;
            *(float2*)(C + (size_t)r * D_ + col) =
                make_float2(c_f[mi][ni][0] + bb.x, c_f[mi][ni][1] + bb.y);
            *(float2*)(C + (size_t)(r + 8) * D_ + col) =
                make_float2(c_f[mi][ni][2] + bb.x, c_f[mi][ni][3] + bb.y);
        }
    }
}

// ---------------------------------------------------------------------------
// Flash attention — round-11 proven optimum: CTA = 64 Q rows x one (b,h),
// 4 warps, 3-stage KV ring, ex2.f16x2 softmax, 4 CTAs/SM.
// ---------------------------------------------------------------------------
#define ASTG 3
#define AK_STRB 144
#define ATILE_BYTES (64*AK_STRB)
#define ASTAGE_BYTES (2*ATILE_BYTES)
#define ATTN_SMEM (ASTG*ASTAGE_BYTES)     // 55296
#define NKT (S_/64)

__device__ __forceinline__ void attn_load_kv(const __half* __restrict__ kg,
                                             const __half* __restrict__ vg,
                                             int kt, char* stage, int tid)
{
    if (kt < NKT) {
        const uint32_t kb = (uint32_t)__cvta_generic_to_shared(stage);
        const uint32_t vb = kb + ATILE_BYTES;
        const char* ksrc = (const char*)(kg + (size_t)kt * 64 * D_);
        const char* vsrc = (const char*)(vg + (size_t)kt * 64 * D_);
#pragma unroll
        for (int i = 0; i < 4; i++) {
            int idx = tid + (i << 7);
            int r = idx >> 3, c16 = idx & 7;
            cp16(kb + (uint32_t)(r * AK_STRB + c16 * 16),
                 ksrc + (size_t)r * (D_*2) + c16 * 16);
        }
#pragma unroll
        for (int i = 0; i < 4; i++) {
            int idx = tid + (i << 7);
            int r = idx >> 3, c16 = idx & 7;
            cp16(vb + (uint32_t)(r * AK_STRB + c16 * 16),
                 vsrc + (size_t)r * (D_*2) + c16 * 16);
        }
    }
    cp_commit();
}

__global__ __launch_bounds__(128, 4)
void attn_mma_kernel(const __half* __restrict__ Q,
                     const __half* __restrict__ Kg,
                     const __half* __restrict__ Vg,
                     __half* __restrict__ O)
{
    extern __shared__ char smraw[];
    const int tid  = threadIdx.x;
    const int lane = tid & 31;
    const int warp = tid >> 5;
    const int gr   = lane >> 2;
    const int lc   = lane & 3;

    const int q0 = blockIdx.x * 64;
    const int bh = blockIdx.y;
    const int b  = bh >> 4;
    const int h  = bh & 15;

    const __half* qg = Q  + ((size_t)(b * S_ + q0)) * D_ + h * HD_;
    const __half* kg = Kg + ((size_t)b * S_) * D_ + h * HD_;
    const __half* vg = Vg + ((size_t)b * S_) * D_ + h * HD_;

    attn_load_kv(kg, vg, 0, smraw, tid);
    attn_load_kv(kg, vg, 1, smraw + ASTAGE_BYTES, tid);

    const uint32_t koff = (uint32_t)(((lane & 7) + ((lane >> 4) << 3)) * AK_STRB
                                     + ((lane >> 3) & 1) * 16);
    const uint32_t voff = (uint32_t)(((lane & 7) + (((lane >> 3) & 1) << 3)) * AK_STRB
                                     + (lane >> 4) * 16);
    const uint32_t smb = (uint32_t)__cvta_generic_to_shared(smraw);

    uint32_t qf[4][4];
    {
        const __half2 sc = __floats2half2_rn(0.125f, 0.125f);
        const __half* q0p = qg + (size_t)(warp * 16 + gr) * D_;
        const __half* q1p = q0p + (size_t)8 * D_;
#pragma unroll
        for (int ks = 0; ks < 4; ks++) {
            const int k0 = ks * 16 + 2 * lc;
            __half2 h0 = __hmul2(*(const __half2*)(q0p + k0), sc);
            __half2 h1 = __hmul2(*(const __half2*)(q1p + k0), sc);
            __half2 h2 = __hmul2(*(const __half2*)(q0p + k0 + 8), sc);
            __half2 h3 = __hmul2(*(const __half2*)(q1p + k0 + 8), sc);
            qf[ks][0] = *(uint32_t*)&h0;
            qf[ks][1] = *(uint32_t*)&h1;
            qf[ks][2] = *(uint32_t*)&h2;
            qf[ks][3] = *(uint32_t*)&h3;
        }
    }

    float co[8][4];
#pragma unroll
    for (int ni = 0; ni < 8; ni++)
#pragma unroll
        for (int j = 0; j < 4; j++) co[ni][j] = 0.f;
    float m0 = -1e30f, m1 = -1e30f, l0 = 0.f, l1 = 0.f;

    const float L2E = 1.4426950408889634f;

    int stg = 0;
    for (int kt = 0; kt < NKT; kt++) {
        cp_wait<1>();
        __syncthreads();

        int wst = stg + 2; if (wst >= ASTG) wst -= ASTG;
        attn_load_kv(kg, vg, kt + 2, smraw + wst * ASTAGE_BYTES, tid);

        const uint32_t Kb = smb + stg * ASTAGE_BYTES;
        const uint32_t Vb = Kb + ATILE_BYTES;

        float c[8][4];
#pragma unroll
        for (int ni = 0; ni < 8; ni++)
#pragma unroll
            for (int j = 0; j < 4; j++) c[ni][j] = 0.f;

#pragma unroll
        for (int ks = 0; ks < 4; ks++) {
#pragma unroll
            for (int p = 0; p < 4; p++) {
                uint32_t br[4];
                ldm_x4(br, Kb + koff + (uint32_t)(p * 16 * AK_STRB + ks * 32));
                mma_f16(c[2*p],   qf[ks], br);
                mma_f16(c[2*p+1], qf[ks], br + 2);
            }
        }

        float mt0 = fmaxf(c[0][0], c[0][1]);
        float mt1 = fmaxf(c[0][2], c[0][3]);
#pragma unroll
        for (int ni = 1; ni < 8; ni++) {
            mt0 = fmaxf(mt0, fmaxf(c[ni][0], c[ni][1]));
            mt1 = fmaxf(mt1, fmaxf(c[ni][2], c[ni][3]));
        }
        mt0 = fmaxf(mt0, __shfl_xor_sync(0xffffffffu, mt0, 1));
        mt0 = fmaxf(mt0, __shfl_xor_sync(0xffffffffu, mt0, 2));
        mt1 = fmaxf(mt1, __shfl_xor_sync(0xffffffffu, mt1, 1));
        mt1 = fmaxf(mt1, __shfl_xor_sync(0xffffffffu, mt1, 2));

        const float mn0 = fmaxf(m0, mt0);
        const float mn1 = fmaxf(m1, mt1);
        const float al0 = __expf(m0 - mn0);
        const float al1 = __expf(m1 - mn1);
        const float bb0 = -mn0 * L2E;
        const float bb1 = -mn1 * L2E;

        uint32_t pr[8][2];
        float rs0 = 0.f, rs1 = 0.f;
#pragma unroll
        for (int ni = 0; ni < 8; ni++) {
            float e0 = fmaf(c[ni][0], L2E, bb0);
            float e1 = fmaf(c[ni][1], L2E, bb0);
            float e2 = fmaf(c[ni][2], L2E, bb1);
            float e3 = fmaf(c[ni][3], L2E, bb1);
            uint32_t p01 = ex2_h2(packh2(e0, e1));
            uint32_t p23 = ex2_h2(packh2(e2, e3));
            pr[ni][0] = p01;
            pr[ni][1] = p23;
            float2 f01 = __half22float2(*(__half2*)&p01);
            float2 f23 = __half22float2(*(__half2*)&p23);
            rs0 += f01.x + f01.y;
            rs1 += f23.x + f23.y;
        }
        rs0 += __shfl_xor_sync(0xffffffffu, rs0, 1);
        rs0 += __shfl_xor_sync(0xffffffffu, rs0, 2);
        rs1 += __shfl_xor_sync(0xffffffffu, rs1, 1);
        rs1 += __shfl_xor_sync(0xffffffffu, rs1, 2);

        l0 = l0 * al0 + rs0;  m0 = mn0;
        l1 = l1 * al1 + rs1;  m1 = mn1;

#pragma unroll
        for (int ni = 0; ni < 8; ni++) {
            co[ni][0] *= al0; co[ni][1] *= al0;
            co[ni][2] *= al1; co[ni][3] *= al1;
        }

#pragma unroll
        for (int ks = 0; ks < 4; ks++) {
            uint32_t af[4];
            af[0] = pr[2*ks][0];
            af[1] = pr[2*ks][1];
            af[2] = pr[2*ks+1][0];
            af[3] = pr[2*ks+1][1];
#pragma unroll
            for (int p = 0; p < 4; p++) {
                uint32_t br[4];
                ldm_x4_t(br, Vb + voff + (uint32_t)(ks * 16 * AK_STRB + p * 32));
                mma_f16(co[2*p],   af, br);
                mma_f16(co[2*p+1], af, br + 2);
            }
        }

        if (++stg == ASTG) stg = 0;
    }

    const float inv0 = 1.f / l0;
    const float inv1 = 1.f / l1;
    const int n0 = b * S_ + q0 + warp * 16 + gr;
#pragma unroll
    for (int ni = 0; ni < 8; ni++) {
        const int col = h * HD_ + ni * 8 + lc * 2;
        *(uint32_t*)(O + (size_t)n0 * D_ + col) =
            packh2(co[ni][0] * inv0, co[ni][1] * inv0);
        *(uint32_t*)(O + (size_t)(n0 + 8) * D_ + col) =
            packh2(co[ni][2] * inv1, co[ni][3] * inv1);
    }
}

// ---------------------------------------------------------------------------
extern "C" void kernel_launch(void* const* d_in, const int* in_sizes, int n_in,
                              void* d_out, int out_size)
{
    const float* x  = (const float*)d_in[0];
    const float* Wq = (const float*)d_in[1];
    const float* bq = (const float*)d_in[2];
    const float* Wk = (const float*)d_in[3];
    const float* bk = (const float*)d_in[4];
    const float* Wv = (const float*)d_in[5];
    const float* bv = (const float*)d_in[6];
    const float* Wo = (const float*)d_in[7];
    const float* bo = (const float*)d_in[8];
    float* out = (float*)d_out;

    __half *xh, *wh3, *wh, *qh, *kh, *vh, *oh;
    cudaGetSymbolAddress((void**)&xh,  g_xh);
    cudaGetSymbolAddress((void**)&wh3, g_wh3);
    cudaGetSymbolAddress((void**)&wh,  g_wh);
    cudaGetSymbolAddress((void**)&qh,  g_qh);
    cudaGetSymbolAddress((void**)&kh,  g_kh);
    cudaGetSymbolAddress((void**)&vh,  g_vh);
    cudaGetSymbolAddress((void**)&oh,  g_oh);

    cudaFuncSetAttribute(gemm_qkv_kernel,
                         cudaFuncAttributeMaxDynamicSharedMemorySize, QKV_SMEM);
    cudaFuncSetAttribute(gemm_o_kernel,
                         cudaFuncAttributeMaxDynamicSharedMemorySize, O_SMEM);
    cudaFuncSetAttribute(attn_mma_kernel,
                         cudaFuncAttributeMaxDynamicSharedMemorySize, ATTN_SMEM);

    const int ntot4 = NX4 + 4 * NW4;
    cvt_all_kernel<<<ntot4 / 256, 256>>>(x, Wq, Wk, Wv, Wo, xh, wh3, wh);

    gemm_qkv_kernel<<<dim3(24, N_ / STM), 256, QKV_SMEM>>>(
        xh, wh3, bq, bk, bv, qh, kh, vh);

    attn_mma_kernel<<<dim3(S_ / 64, B_ * H_), 128, ATTN_SMEM>>>(qh, kh, vh, oh);

    gemm_o_kernel<<<dim3(D_ / OTN, N_ / OTM), 256, O_SMEM>>>(oh, wh, bo, out);
}